// round 3
// baseline (speedup 1.0000x reference)
#include <cuda_runtime.h>
#include <cuda_bf16.h>
#include <math.h>

// Problem constants
#define BATCH   2
#define LSEQ    2048
#define DMODEL  1024
#define DINNER  2048
#define NSTATE  16
#define KCONV   4
#define MTOT    (BATCH * LSEQ)      // 4096

// ---------------------------------------------------------------------------
// Static scratch (no allocations allowed)
// ---------------------------------------------------------------------------
__device__ float g_xz[MTOT * DINNER];      // in-proj output
__device__ float g_xg[MTOT * DINNER];      // gate-proj output
__device__ float g_act[MTOT * DINNER];     // silu(conv(xz))
__device__ float g_delta[MTOT * DINNER];   // softplus(act @ W_delta + b)
__device__ float g_Bm[MTOT * NSTATE];
__device__ float g_Cm[MTOT * NSTATE];
__device__ float g_gated[MTOT * DINNER];   // (ssm_out) * silu(x_gate)

// ---------------------------------------------------------------------------
// Tiled fp32 GEMM: C[M,N] = A[M,K] @ B[K,N] + bias[N], optional softplus.
// BM=BN=128, BK=8, 256 threads, 8x8 per-thread microtile.
// Requires M%128==0, N%128==0, K%8==0 (true for all our shapes).
// ---------------------------------------------------------------------------
template<int EPI>  // 0: bias only, 1: bias + softplus
__global__ __launch_bounds__(256)
void sgemm128(const float* __restrict__ A, const float* __restrict__ B,
              const float* __restrict__ bias, float* __restrict__ C,
              int M, int N, int K)
{
    __shared__ float As[8][128];
    __shared__ float Bs[8][128];

    const int tid = threadIdx.x;
    const int bx = blockIdx.x;        // N direction
    const int by = blockIdx.y;        // M direction
    const int tx = tid & 15;          // 16 threads in N dir
    const int ty = tid >> 4;          // 16 threads in M dir

    // A-tile loader: 128 rows x 8 cols, one float4 per thread
    const int arow = tid >> 1;
    const int acol = (tid & 1) * 4;
    // B-tile loader: 8 rows x 128 cols, one float4 per thread
    const int brow = tid >> 5;
    const int bcol = (tid & 31) * 4;

    const float* Ap = A + (size_t)(by * 128 + arow) * K + acol;
    const float* Bp = B + (size_t)brow * N + (size_t)bx * 128 + bcol;

    float acc[8][8];
#pragma unroll
    for (int i = 0; i < 8; i++)
#pragma unroll
        for (int j = 0; j < 8; j++) acc[i][j] = 0.f;

    for (int k0 = 0; k0 < K; k0 += 8) {
        float4 a4 = *(const float4*)Ap;
        float4 b4 = *(const float4*)Bp;
        As[acol + 0][arow] = a4.x;
        As[acol + 1][arow] = a4.y;
        As[acol + 2][arow] = a4.z;
        As[acol + 3][arow] = a4.w;
        *(float4*)&Bs[brow][bcol] = b4;
        __syncthreads();

#pragma unroll
        for (int k = 0; k < 8; k++) {
            float ar[8], br[8];
#pragma unroll
            for (int i = 0; i < 8; i++) ar[i] = As[k][ty * 8 + i];
#pragma unroll
            for (int j = 0; j < 8; j++) br[j] = Bs[k][tx * 8 + j];
#pragma unroll
            for (int i = 0; i < 8; i++)
#pragma unroll
                for (int j = 0; j < 8; j++)
                    acc[i][j] = fmaf(ar[i], br[j], acc[i][j]);
        }
        __syncthreads();
        Ap += 8;
        Bp += (size_t)8 * N;
    }

    const int col0 = bx * 128 + tx * 8;
    float bv[8];
#pragma unroll
    for (int j = 0; j < 8; j++) bv[j] = __ldg(bias + col0 + j);

#pragma unroll
    for (int i = 0; i < 8; i++) {
        const int row = by * 128 + ty * 8 + i;
        float* cp = C + (size_t)row * N + col0;
        float o[8];
#pragma unroll
        for (int j = 0; j < 8; j++) {
            float v = acc[i][j] + bv[j];
            if (EPI == 1) {
                // softplus, accurate branch for large v
                v = (v > 20.f) ? v : log1pf(expf(v));
            }
            o[j] = v;
        }
        *(float4*)(cp + 0) = make_float4(o[0], o[1], o[2], o[3]);
        *(float4*)(cp + 4) = make_float4(o[4], o[5], o[6], o[7]);
    }
}

// ---------------------------------------------------------------------------
// Causal depthwise conv (K=4) + bias + silu, fused.
// ---------------------------------------------------------------------------
__global__ __launch_bounds__(256)
void conv_silu(const float* __restrict__ xz, const float* __restrict__ w,
               const float* __restrict__ cb, float* __restrict__ act)
{
    const int idx = blockIdx.x * 256 + threadIdx.x;   // over MTOT*DINNER
    if (idx >= MTOT * DINNER) return;
    const int d = idx & (DINNER - 1);
    const int bt = idx >> 11;            // b*L + t  (DINNER = 2^11)
    const int t = bt & (LSEQ - 1);

    float s = __ldg(cb + d);
#pragma unroll
    for (int k = 0; k < KCONV; k++) {
        const int tt = t - (KCONV - 1) + k;
        if (tt >= 0)
            s = fmaf(__ldg(w + d * KCONV + k), xz[idx + (k - (KCONV - 1)) * DINNER], s);
    }
    act[idx] = s / (1.f + __expf(-s));   // silu
}

// ---------------------------------------------------------------------------
// Skinny GEMM: Bm = act @ W_B, Cm = act @ W_C   (N=16 each, fused).
// One block handles 16 rows; thread layout (m_local = tid>>4, n = tid&15).
// ---------------------------------------------------------------------------
__global__ __launch_bounds__(256)
void bc_gemm(const float* __restrict__ act,
             const float* __restrict__ WB, const float* __restrict__ WC,
             float* __restrict__ Bm, float* __restrict__ Cm)
{
    const int m = blockIdx.x * 16 + (threadIdx.x >> 4);
    const int n = threadIdx.x & 15;
    const float* a = act + (size_t)m * DINNER;

    float sb = 0.f, sc = 0.f;
#pragma unroll 4
    for (int k = 0; k < DINNER; k++) {
        const float av = a[k];
        sb = fmaf(av, __ldg(WB + k * NSTATE + n), sb);
        sc = fmaf(av, __ldg(WC + k * NSTATE + n), sc);
    }
    Bm[m * NSTATE + n] = sb;
    Cm[m * NSTATE + n] = sc;
}

// ---------------------------------------------------------------------------
// Selective scan + skip + gating, fused.
// One warp handles two channels d (lanes 0-15 -> d0, lanes 16-31 -> d1),
// lane%16 = state index n. State h lives in a register; y via shfl reduce.
// ---------------------------------------------------------------------------
__global__ __launch_bounds__(256)
void scan_kernel(const float* __restrict__ delta, const float* __restrict__ act,
                 const float* __restrict__ Bm, const float* __restrict__ Cm,
                 const float* __restrict__ A_log, const float* __restrict__ D_skip,
                 const float* __restrict__ xg, float* __restrict__ gated)
{
    const int w = blockIdx.x * 8 + (threadIdx.x >> 5);   // 0 .. 2047
    const int lane = threadIdx.x & 31;
    const int n = lane & 15;
    const int b = w >> 10;                 // DINNER/2 = 1024 warps per batch
    const int dp = w & 1023;
    const int d = dp * 2 + (lane >> 4);

    const float a = -expf(A_log[d * NSTATE + n]);
    const float dsk = D_skip[d];

    const float* pD = delta + (size_t)b * LSEQ * DINNER + d;
    const float* pX = act   + (size_t)b * LSEQ * DINNER + d;
    const float* pG = xg    + (size_t)b * LSEQ * DINNER + d;
    float*       pO = gated + (size_t)b * LSEQ * DINNER + d;
    const float* pB = Bm + (size_t)b * LSEQ * NSTATE + n;
    const float* pC = Cm + (size_t)b * LSEQ * NSTATE + n;

    float h = 0.f;
    for (int t = 0; t < LSEQ; t++) {
        const float dt = pD[(size_t)t * DINNER];          // softplus applied
        const float xv = pX[(size_t)t * DINNER];
        const float Bv = pB[t * NSTATE];
        const float Cv = pC[t * NSTATE];

        const float dA = __expf(dt * a);
        h = fmaf(dA, h, (dt * xv) * Bv);

        float p = h * Cv;
        p += __shfl_xor_sync(0xffffffffu, p, 1);
        p += __shfl_xor_sync(0xffffffffu, p, 2);
        p += __shfl_xor_sync(0xffffffffu, p, 4);
        p += __shfl_xor_sync(0xffffffffu, p, 8);

        if (n == 0) {
            const float g = pG[(size_t)t * DINNER];
            const float y = p + xv * dsk;
            pO[(size_t)t * DINNER] = y * (g / (1.f + __expf(-g)));  // y*silu(g)
        }
    }
}

// ---------------------------------------------------------------------------
// Launch
// ---------------------------------------------------------------------------
extern "C" void kernel_launch(void* const* d_in, const int* in_sizes, int n_in,
                              void* d_out, int out_size)
{
    const float* x      = (const float*)d_in[0];   // (B,L,DMODEL)
    const float* W_in   = (const float*)d_in[1];   // (DMODEL, DINNER)
    const float* b_in   = (const float*)d_in[2];
    const float* W_gate = (const float*)d_in[3];
    const float* b_gate = (const float*)d_in[4];
    const float* conv_w = (const float*)d_in[5];   // (DINNER,1,K)
    const float* conv_b = (const float*)d_in[6];
    const float* A_log  = (const float*)d_in[7];   // (DINNER, NSTATE)
    const float* D_skip = (const float*)d_in[8];
    const float* W_delta= (const float*)d_in[9];   // (DINNER, DINNER)
    const float* b_delta= (const float*)d_in[10];
    const float* W_B    = (const float*)d_in[11];  // (DINNER, NSTATE)
    const float* W_C    = (const float*)d_in[12];
    const float* W_out  = (const float*)d_in[13];  // (DINNER, DMODEL)
    const float* b_out  = (const float*)d_in[14];
    float* out = (float*)d_out;                    // (B,L,DMODEL)

    float* xz    = nullptr; cudaGetSymbolAddress((void**)&xz,    g_xz);
    float* xg    = nullptr; cudaGetSymbolAddress((void**)&xg,    g_xg);
    float* act   = nullptr; cudaGetSymbolAddress((void**)&act,   g_act);
    float* delt  = nullptr; cudaGetSymbolAddress((void**)&delt,  g_delta);
    float* Bm    = nullptr; cudaGetSymbolAddress((void**)&Bm,    g_Bm);
    float* Cm    = nullptr; cudaGetSymbolAddress((void**)&Cm,    g_Cm);
    float* gated = nullptr; cudaGetSymbolAddress((void**)&gated, g_gated);

    // 1) xz = x @ W_in + b_in           M=4096 N=2048 K=1024
    {
        dim3 grid(DINNER / 128, MTOT / 128);
        sgemm128<0><<<grid, 256>>>(x, W_in, b_in, xz, MTOT, DINNER, DMODEL);
    }
    // 2) x_gate = x @ W_gate + b_gate
    {
        dim3 grid(DINNER / 128, MTOT / 128);
        sgemm128<0><<<grid, 256>>>(x, W_gate, b_gate, xg, MTOT, DINNER, DMODEL);
    }
    // 3) act = silu(conv(xz) + conv_b)
    {
        const int total = MTOT * DINNER;
        conv_silu<<<(total + 255) / 256, 256>>>(xz, conv_w, conv_b, act);
    }
    // 4) delta = softplus(act @ W_delta + b_delta)   M=4096 N=2048 K=2048
    {
        dim3 grid(DINNER / 128, MTOT / 128);
        sgemm128<1><<<grid, 256>>>(act, W_delta, b_delta, delt, MTOT, DINNER, DINNER);
    }
    // 5) Bm = act @ W_B ; Cm = act @ W_C
    {
        bc_gemm<<<MTOT / 16, 256>>>(act, W_B, W_C, Bm, Cm);
    }
    // 6) selective scan + skip + gating -> gated
    {
        scan_kernel<<<(BATCH * DINNER / 2) / 8, 256>>>(delt, act, Bm, Cm,
                                                       A_log, D_skip, xg, gated);
    }
    // 7) out = gated @ W_out + b_out    M=4096 N=1024 K=2048
    {
        dim3 grid(DMODEL / 128, MTOT / 128);
        sgemm128<0><<<grid, 256>>>(gated, W_out, b_out, out, MTOT, DMODEL, DINNER);
    }
}

// round 10
// speedup vs baseline: 2.5389x; 2.5389x over previous
#include <cuda_runtime.h>
#include <cuda_bf16.h>
#include <math.h>
#include <stdint.h>

// Problem constants
#define BATCH   2
#define LSEQ    2048
#define DMODEL  1024
#define DINNER  2048
#define NSTATE  16
#define KCONV   4
#define MTOT    (BATCH * LSEQ)      // 4096

// ---------------------------------------------------------------------------
// Static scratch (no allocations allowed)
// ---------------------------------------------------------------------------
__device__ float g_xz[MTOT * DINNER];
__device__ float g_xg[MTOT * DINNER];
__device__ float g_act[MTOT * DINNER];
__device__ float g_delta[MTOT * DINNER];
__device__ float g_Bm[MTOT * NSTATE];
__device__ float g_Cm[MTOT * NSTATE];
__device__ float g_gated[MTOT * DINNER];

// bf16 split operands
__device__ __nv_bfloat16 g_xh[MTOT * DMODEL];
__device__ __nv_bfloat16 g_xl[MTOT * DMODEL];
__device__ __nv_bfloat16 g_ah[MTOT * DINNER];
__device__ __nv_bfloat16 g_al[MTOT * DINNER];
__device__ __nv_bfloat16 g_gh[MTOT * DINNER];
__device__ __nv_bfloat16 g_gl[MTOT * DINNER];
// transposed weight buffer (reused sequentially for all 4 weight matrices)
__device__ __nv_bfloat16 g_wth[DINNER * DINNER];
__device__ __nv_bfloat16 g_wtl[DINNER * DINNER];

// ---------------------------------------------------------------------------
// PTX helpers — sm_80-class path only (ldmatrix / mma.sync / cp.async),
// all supported on base sm_100 target.
// ---------------------------------------------------------------------------
__device__ __forceinline__ uint32_t smem_u32(const void* p) {
    uint32_t a;
    asm("{ .reg .u64 t; cvta.to.shared.u64 t, %1; cvt.u32.u64 %0, t; }"
        : "=r"(a) : "l"(p));
    return a;
}
__device__ __forceinline__ void cpa16(uint32_t dst, const void* src) {
    asm volatile("cp.async.cg.shared.global [%0], [%1], 16;"
                 :: "r"(dst), "l"(src));
}
__device__ __forceinline__ void ldsm4(uint32_t addr, uint32_t* q) {
    asm volatile("ldmatrix.sync.aligned.m8n8.x4.shared.b16 {%0,%1,%2,%3}, [%4];"
                 : "=r"(q[0]), "=r"(q[1]), "=r"(q[2]), "=r"(q[3]) : "r"(addr));
}
__device__ __forceinline__ void mma16816(float* d, const uint32_t* a,
                                         uint32_t b0, uint32_t b1) {
    asm volatile(
        "mma.sync.aligned.m16n8k16.row.col.f32.bf16.bf16.f32 "
        "{%0,%1,%2,%3}, {%4,%5,%6,%7}, {%8,%9}, {%0,%1,%2,%3};"
        : "+f"(d[0]), "+f"(d[1]), "+f"(d[2]), "+f"(d[3])
        : "r"(a[0]), "r"(a[1]), "r"(a[2]), "r"(a[3]), "r"(b0), "r"(b1));
}

// Swizzle for 32-byte rows (16 bf16): flip 16B-chunk bit by row bit 2.
// Conflict-free for 16B stores and ldmatrix 8-row reads (all 8 bank groups hit).
#define SWZ32(o) ((o) ^ (((o) >> 3) & 0x10))

// ---------------------------------------------------------------------------
// mma.sync GEMM: C[M,N] = sum_k A[m,k]*B[n,k] + bias[n]   (A:[M,K], B:[N,K])
// A = Ah+Al, B = Bh+Bl (bf16 split), 3 MMA terms (drop Al*Bl).
// Tile 128x128, BK=16, 2-stage cp.async pipeline, 8 warps (2x4), warp 64x32.
// Static shared memory only (32 KB) — no dynamic smem, no attribute calls.
// ---------------------------------------------------------------------------
#define MG_STAGE  16384        // Ah(4K) Al(4K) Bh(4K) Bl(4K)

__device__ __forceinline__ void load_stage(uint32_t sstage,
        const __nv_bfloat16* __restrict__ Ah, const __nv_bfloat16* __restrict__ Al,
        const __nv_bfloat16* __restrict__ Bh, const __nv_bfloat16* __restrict__ Bl,
        int arow0, int brow0, int K, int kc, int tid)
{
    const int rr = tid >> 1;          // row 0..127
    const int cp = tid & 1;           // 16B chunk in 32B row
    const uint32_t soff = SWZ32(rr * 32 + cp * 16);
    const size_t ga = (size_t)(arow0 + rr) * K + kc + cp * 8;
    const size_t gb = (size_t)(brow0 + rr) * K + kc + cp * 8;
    cpa16(sstage +         soff, Ah + ga);
    cpa16(sstage + 4096  + soff, Al + ga);
    cpa16(sstage + 8192  + soff, Bh + gb);
    cpa16(sstage + 12288 + soff, Bl + gb);
}

template<int EPI>   // 0: bias, 1: bias + softplus
__global__ __launch_bounds__(256, 2)
void mmagemm(const __nv_bfloat16* __restrict__ Ah, const __nv_bfloat16* __restrict__ Al,
             const __nv_bfloat16* __restrict__ Bh, const __nv_bfloat16* __restrict__ Bl,
             const float* __restrict__ bias, float* __restrict__ C,
             int N, int K)
{
    __shared__ char smem[2 * MG_STAGE];     // 32 KB static
    const uint32_t sb = smem_u32(smem);
    const int tid  = threadIdx.x;
    const int wid  = tid >> 5;
    const int lane = tid & 31;
    const int warp_m = wid & 1;          // 2 warps in M
    const int warp_n = wid >> 1;         // 4 warps in N
    const int arow0 = blockIdx.y * 128;
    const int brow0 = blockIdx.x * 128;

    // ldmatrix per-lane address components (j = matrix index group, r = row)
    const int j = lane >> 3, r = lane & 7;
    const int a_row  = warp_m * 64 + ((j & 1) << 3) + r;   // + mt*16
    const int a_kb16 = (j >> 1) << 4;                      // byte offset of k-half
    const int b_row  = warp_n * 32 + ((j >> 1) << 3) + r;  // + nt16*16
    const int b_kb16 = (j & 1) << 4;

    float acc[4][4][4];
#pragma unroll
    for (int a = 0; a < 4; a++)
#pragma unroll
        for (int b = 0; b < 4; b++)
#pragma unroll
            for (int c = 0; c < 4; c++) acc[a][b][c] = 0.f;

    const int nch = K >> 4;

    load_stage(sb, Ah, Al, Bh, Bl, arow0, brow0, K, 0, tid);
    asm volatile("cp.async.commit_group;");

    for (int i = 0; i < nch; i++) {
        if (i + 1 < nch) {
            load_stage(sb + ((i + 1) & 1) * MG_STAGE, Ah, Al, Bh, Bl,
                       arow0, brow0, K, (i + 1) * 16, tid);
            asm volatile("cp.async.commit_group;");
            asm volatile("cp.async.wait_group 1;");
        } else {
            asm volatile("cp.async.wait_group 0;");
        }
        __syncthreads();

        const uint32_t st = sb + (i & 1) * MG_STAGE;

        uint32_t bh[2][4], bl[2][4];
#pragma unroll
        for (int nt16 = 0; nt16 < 2; nt16++) {
            const uint32_t boff = SWZ32((b_row + nt16 * 16) * 32 + b_kb16);
            ldsm4(st + 8192  + boff, bh[nt16]);
            ldsm4(st + 12288 + boff, bl[nt16]);
        }
#pragma unroll
        for (int mt = 0; mt < 4; mt++) {
            const uint32_t aoff = SWZ32((a_row + mt * 16) * 32 + a_kb16);
            uint32_t ahf[4], alf[4];
            ldsm4(st +        aoff, ahf);
            ldsm4(st + 4096 + aoff, alf);
#pragma unroll
            for (int nt = 0; nt < 4; nt++) {
                const uint32_t b0h = bh[nt >> 1][(nt & 1) * 2];
                const uint32_t b1h = bh[nt >> 1][(nt & 1) * 2 + 1];
                const uint32_t b0l = bl[nt >> 1][(nt & 1) * 2];
                const uint32_t b1l = bl[nt >> 1][(nt & 1) * 2 + 1];
                mma16816(acc[mt][nt], ahf, b0h, b1h);
                mma16816(acc[mt][nt], ahf, b0l, b1l);
                mma16816(acc[mt][nt], alf, b0h, b1h);
            }
        }
        __syncthreads();   // protect stage about to be overwritten
    }

    // Epilogue
    const int gid = lane >> 2, tig = lane & 3;
#pragma unroll
    for (int mt = 0; mt < 4; mt++) {
        const int r0 = arow0 + warp_m * 64 + mt * 16 + gid;
#pragma unroll
        for (int nt = 0; nt < 4; nt++) {
            const int col = brow0 + warp_n * 32 + nt * 8 + tig * 2;
            const float bb0 = __ldg(bias + col);
            const float bb1 = __ldg(bias + col + 1);
            float v0 = acc[mt][nt][0] + bb0;
            float v1 = acc[mt][nt][1] + bb1;
            float v2 = acc[mt][nt][2] + bb0;
            float v3 = acc[mt][nt][3] + bb1;
            if (EPI == 1) {
                v0 = (v0 > 20.f) ? v0 : log1pf(expf(v0));
                v1 = (v1 > 20.f) ? v1 : log1pf(expf(v1));
                v2 = (v2 > 20.f) ? v2 : log1pf(expf(v2));
                v3 = (v3 > 20.f) ? v3 : log1pf(expf(v3));
            }
            float2 p01; p01.x = v0; p01.y = v1;
            float2 p23; p23.x = v2; p23.y = v3;
            *(float2*)(C + (size_t)r0 * N + col)       = p01;
            *(float2*)(C + (size_t)(r0 + 8) * N + col) = p23;
        }
    }
}

// ---------------------------------------------------------------------------
// Elementwise bf16 split: in(fp32) -> hi, lo (bf16), 4 elems/thread
// ---------------------------------------------------------------------------
__global__ __launch_bounds__(256)
void split_bf16(const float* __restrict__ in, __nv_bfloat16* __restrict__ hi,
                __nv_bfloat16* __restrict__ lo, int n4)
{
    const int i = blockIdx.x * 256 + threadIdx.x;
    if (i >= n4) return;
    float4 v = ((const float4*)in)[i];
    float f[4] = {v.x, v.y, v.z, v.w};
    __nv_bfloat16 h[4], l[4];
#pragma unroll
    for (int j = 0; j < 4; j++) {
        h[j] = __float2bfloat16(f[j]);
        l[j] = __float2bfloat16(f[j] - __bfloat162float(h[j]));
    }
    __nv_bfloat162 H0, H1, L0, L1;
    H0.x = h[0]; H0.y = h[1]; H1.x = h[2]; H1.y = h[3];
    L0.x = l[0]; L0.y = l[1]; L1.x = l[2]; L1.y = l[3];
    ((__nv_bfloat162*)hi)[i * 2]     = H0;
    ((__nv_bfloat162*)hi)[i * 2 + 1] = H1;
    ((__nv_bfloat162*)lo)[i * 2]     = L0;
    ((__nv_bfloat162*)lo)[i * 2 + 1] = L1;
}

// ---------------------------------------------------------------------------
// Weight transpose + bf16 split: W[K,N] -> Th[N,K], Tl[N,K]
// ---------------------------------------------------------------------------
__global__ void transpose_split(const float* __restrict__ W, int K, int N,
                                __nv_bfloat16* __restrict__ Th,
                                __nv_bfloat16* __restrict__ Tl)
{
    __shared__ float ts[32][33];
    const int n0 = blockIdx.x * 32, k0 = blockIdx.y * 32;
    const int tx = threadIdx.x, ty = threadIdx.y;
#pragma unroll
    for (int i = 0; i < 4; i++)
        ts[ty + i * 8][tx] = W[(size_t)(k0 + ty + i * 8) * N + n0 + tx];
    __syncthreads();
#pragma unroll
    for (int i = 0; i < 4; i++) {
        float v = ts[tx][ty + i * 8];
        __nv_bfloat16 h = __float2bfloat16(v);
        __nv_bfloat16 l = __float2bfloat16(v - __bfloat162float(h));
        size_t o = (size_t)(n0 + ty + i * 8) * K + k0 + tx;
        Th[o] = h;
        Tl[o] = l;
    }
}

// ---------------------------------------------------------------------------
// Causal depthwise conv (K=4) + bias + silu
// ---------------------------------------------------------------------------
__global__ __launch_bounds__(256)
void conv_silu(const float* __restrict__ xz, const float* __restrict__ w,
               const float* __restrict__ cb, float* __restrict__ act)
{
    const int idx = blockIdx.x * 256 + threadIdx.x;
    if (idx >= MTOT * DINNER) return;
    const int d = idx & (DINNER - 1);
    const int bt = idx >> 11;
    const int t = bt & (LSEQ - 1);

    float s = __ldg(cb + d);
#pragma unroll
    for (int k = 0; k < KCONV; k++) {
        const int tt = t - (KCONV - 1) + k;
        if (tt >= 0)
            s = fmaf(__ldg(w + d * KCONV + k), xz[idx + (k - (KCONV - 1)) * DINNER], s);
    }
    act[idx] = s / (1.f + __expf(-s));
}

// ---------------------------------------------------------------------------
// Skinny GEMM: Bm = act @ W_B, Cm = act @ W_C
// ---------------------------------------------------------------------------
__global__ __launch_bounds__(256)
void bc_gemm(const float* __restrict__ act,
             const float* __restrict__ WB, const float* __restrict__ WC,
             float* __restrict__ Bm, float* __restrict__ Cm)
{
    const int m = blockIdx.x * 16 + (threadIdx.x >> 4);
    const int n = threadIdx.x & 15;
    const float* a = act + (size_t)m * DINNER;

    float sb = 0.f, sc = 0.f;
#pragma unroll 8
    for (int k = 0; k < DINNER; k++) {
        const float av = a[k];
        sb = fmaf(av, __ldg(WB + k * NSTATE + n), sb);
        sc = fmaf(av, __ldg(WC + k * NSTATE + n), sc);
    }
    Bm[m * NSTATE + n] = sb;
    Cm[m * NSTATE + n] = sc;
}

// ---------------------------------------------------------------------------
// Selective scan + skip + gating, 8-timestep batched loads (MLP=8)
// ---------------------------------------------------------------------------
__global__ __launch_bounds__(256)
void scan_kernel(const float* __restrict__ delta, const float* __restrict__ act,
                 const float* __restrict__ Bm, const float* __restrict__ Cm,
                 const float* __restrict__ A_log, const float* __restrict__ D_skip,
                 const float* __restrict__ xg, float* __restrict__ gated)
{
    const int w = blockIdx.x * 8 + (threadIdx.x >> 5);   // 0 .. 2047
    const int lane = threadIdx.x & 31;
    const int n = lane & 15;
    const int b = w >> 10;
    const int dp = w & 1023;
    const int d = dp * 2 + (lane >> 4);

    const float a = -expf(A_log[d * NSTATE + n]);
    const float dsk = D_skip[d];

    const float* pD = delta + (size_t)b * LSEQ * DINNER + d;
    const float* pX = act   + (size_t)b * LSEQ * DINNER + d;
    const float* pG = xg    + (size_t)b * LSEQ * DINNER + d;
    float*       pO = gated + (size_t)b * LSEQ * DINNER + d;
    const float* pB = Bm + (size_t)b * LSEQ * NSTATE + n;
    const float* pC = Cm + (size_t)b * LSEQ * NSTATE + n;

    float h = 0.f;
    for (int t0 = 0; t0 < LSEQ; t0 += 8) {
        float dv[8], xv[8], gv[8], bv[8], cv[8];
#pragma unroll
        for (int jj = 0; jj < 8; jj++) {
            const size_t o = (size_t)(t0 + jj) * DINNER;
            dv[jj] = pD[o];
            xv[jj] = pX[o];
            gv[jj] = pG[o];
            bv[jj] = pB[(t0 + jj) * NSTATE];
            cv[jj] = pC[(t0 + jj) * NSTATE];
        }
#pragma unroll
        for (int jj = 0; jj < 8; jj++) {
            const float dA = __expf(dv[jj] * a);
            h = fmaf(dA, h, (dv[jj] * xv[jj]) * bv[jj]);
            float p = h * cv[jj];
            p += __shfl_xor_sync(0xffffffffu, p, 1);
            p += __shfl_xor_sync(0xffffffffu, p, 2);
            p += __shfl_xor_sync(0xffffffffu, p, 4);
            p += __shfl_xor_sync(0xffffffffu, p, 8);
            if (n == 0) {
                const float g = gv[jj];
                const float y = p + xv[jj] * dsk;
                pO[(size_t)(t0 + jj) * DINNER] = y * (g / (1.f + __expf(-g)));
            }
        }
    }
}

// ---------------------------------------------------------------------------
// Launch
// ---------------------------------------------------------------------------
extern "C" void kernel_launch(void* const* d_in, const int* in_sizes, int n_in,
                              void* d_out, int out_size)
{
    const float* x      = (const float*)d_in[0];
    const float* W_in   = (const float*)d_in[1];
    const float* b_in   = (const float*)d_in[2];
    const float* W_gate = (const float*)d_in[3];
    const float* b_gate = (const float*)d_in[4];
    const float* conv_w = (const float*)d_in[5];
    const float* conv_b = (const float*)d_in[6];
    const float* A_log  = (const float*)d_in[7];
    const float* D_skip = (const float*)d_in[8];
    const float* W_delta= (const float*)d_in[9];
    const float* b_delta= (const float*)d_in[10];
    const float* W_B    = (const float*)d_in[11];
    const float* W_C    = (const float*)d_in[12];
    const float* W_out  = (const float*)d_in[13];
    const float* b_out  = (const float*)d_in[14];
    float* out = (float*)d_out;

    float *xz, *xg, *act, *delt, *Bm, *Cm, *gated;
    cudaGetSymbolAddress((void**)&xz,    g_xz);
    cudaGetSymbolAddress((void**)&xg,    g_xg);
    cudaGetSymbolAddress((void**)&act,   g_act);
    cudaGetSymbolAddress((void**)&delt,  g_delta);
    cudaGetSymbolAddress((void**)&Bm,    g_Bm);
    cudaGetSymbolAddress((void**)&Cm,    g_Cm);
    cudaGetSymbolAddress((void**)&gated, g_gated);

    __nv_bfloat16 *xh, *xl, *ah, *al, *gh, *gl, *wth, *wtl;
    cudaGetSymbolAddress((void**)&xh,  g_xh);
    cudaGetSymbolAddress((void**)&xl,  g_xl);
    cudaGetSymbolAddress((void**)&ah,  g_ah);
    cudaGetSymbolAddress((void**)&al,  g_al);
    cudaGetSymbolAddress((void**)&gh,  g_gh);
    cudaGetSymbolAddress((void**)&gl,  g_gl);
    cudaGetSymbolAddress((void**)&wth, g_wth);
    cudaGetSymbolAddress((void**)&wtl, g_wtl);

    // 0) split x -> bf16 hi/lo
    {
        const int n4 = MTOT * DMODEL / 4;
        split_bf16<<<(n4 + 255) / 256, 256>>>(x, xh, xl, n4);
    }
    // 1) xz = x @ W_in + b_in
    {
        dim3 tg(DINNER / 32, DMODEL / 32);
        transpose_split<<<tg, dim3(32, 8)>>>(W_in, DMODEL, DINNER, wth, wtl);
        dim3 grid(DINNER / 128, MTOT / 128);
        mmagemm<0><<<grid, 256>>>(xh, xl, wth, wtl, b_in, xz, DINNER, DMODEL);
    }
    // 2) x_gate = x @ W_gate + b_gate
    {
        dim3 tg(DINNER / 32, DMODEL / 32);
        transpose_split<<<tg, dim3(32, 8)>>>(W_gate, DMODEL, DINNER, wth, wtl);
        dim3 grid(DINNER / 128, MTOT / 128);
        mmagemm<0><<<grid, 256>>>(xh, xl, wth, wtl, b_gate, xg, DINNER, DMODEL);
    }
    // 3) act = silu(conv(xz) + conv_b)
    {
        const int total = MTOT * DINNER;
        conv_silu<<<(total + 255) / 256, 256>>>(xz, conv_w, conv_b, act);
    }
    // 4) delta = softplus(act @ W_delta + b_delta)
    {
        const int n4 = MTOT * DINNER / 4;
        split_bf16<<<(n4 + 255) / 256, 256>>>(act, ah, al, n4);
        dim3 tg(DINNER / 32, DINNER / 32);
        transpose_split<<<tg, dim3(32, 8)>>>(W_delta, DINNER, DINNER, wth, wtl);
        dim3 grid(DINNER / 128, MTOT / 128);
        mmagemm<1><<<grid, 256>>>(ah, al, wth, wtl, b_delta, delt, DINNER, DINNER);
    }
    // 5) Bm, Cm
    {
        bc_gemm<<<MTOT / 16, 256>>>(act, W_B, W_C, Bm, Cm);
    }
    // 6) scan + skip + gating
    {
        scan_kernel<<<(BATCH * DINNER / 2) / 8, 256>>>(delt, act, Bm, Cm,
                                                       A_log, D_skip, xg, gated);
    }
    // 7) out = gated @ W_out + b_out
    {
        const int n4 = MTOT * DINNER / 4;
        split_bf16<<<(n4 + 255) / 256, 256>>>(gated, gh, gl, n4);
        dim3 tg(DMODEL / 32, DINNER / 32);
        transpose_split<<<tg, dim3(32, 8)>>>(W_out, DINNER, DMODEL, wth, wtl);
        dim3 grid(DMODEL / 128, MTOT / 128);
        mmagemm<0><<<grid, 256>>>(gh, gl, wth, wtl, b_out, out, DMODEL, DINNER);
    }
}

// round 11
// speedup vs baseline: 2.5839x; 1.0177x over previous
#include <cuda_runtime.h>
#include <cuda_bf16.h>
#include <math.h>
#include <stdint.h>

// Problem constants
#define BATCH   2
#define LSEQ    2048
#define DMODEL  1024
#define DINNER  2048
#define NSTATE  16
#define KCONV   4
#define MTOT    (BATCH * LSEQ)      // 4096

// ---------------------------------------------------------------------------
// Static scratch (no allocations allowed)
// ---------------------------------------------------------------------------
__device__ float g_xz[MTOT * DINNER];
__device__ float g_xg[MTOT * DINNER];
__device__ float g_act[MTOT * DINNER];
__device__ float g_delta[MTOT * DINNER];
__device__ float g_Bm[MTOT * NSTATE];
__device__ float g_Cm[MTOT * NSTATE];

// bf16 split operands
__device__ __nv_bfloat16 g_xh[MTOT * DMODEL];
__device__ __nv_bfloat16 g_xl[MTOT * DMODEL];
__device__ __nv_bfloat16 g_ah[MTOT * DINNER];
__device__ __nv_bfloat16 g_al[MTOT * DINNER];
__device__ __nv_bfloat16 g_gh[MTOT * DINNER];
__device__ __nv_bfloat16 g_gl[MTOT * DINNER];
// transposed weight buffer (4096x1024 for fused in+gate; reused for others)
__device__ __nv_bfloat16 g_wth[DINNER * DINNER];
__device__ __nv_bfloat16 g_wtl[DINNER * DINNER];

// ---------------------------------------------------------------------------
// PTX helpers — sm_80-class path (ldmatrix / mma.sync / cp.async)
// ---------------------------------------------------------------------------
__device__ __forceinline__ uint32_t smem_u32(const void* p) {
    uint32_t a;
    asm("{ .reg .u64 t; cvta.to.shared.u64 t, %1; cvt.u32.u64 %0, t; }"
        : "=r"(a) : "l"(p));
    return a;
}
__device__ __forceinline__ void cpa16(uint32_t dst, const void* src) {
    asm volatile("cp.async.cg.shared.global [%0], [%1], 16;"
                 :: "r"(dst), "l"(src));
}
__device__ __forceinline__ void ldsm4(uint32_t addr, uint32_t* q) {
    asm volatile("ldmatrix.sync.aligned.m8n8.x4.shared.b16 {%0,%1,%2,%3}, [%4];"
                 : "=r"(q[0]), "=r"(q[1]), "=r"(q[2]), "=r"(q[3]) : "r"(addr));
}
__device__ __forceinline__ void mma16816(float* d, const uint32_t* a,
                                         uint32_t b0, uint32_t b1) {
    asm volatile(
        "mma.sync.aligned.m16n8k16.row.col.f32.bf16.bf16.f32 "
        "{%0,%1,%2,%3}, {%4,%5,%6,%7}, {%8,%9}, {%0,%1,%2,%3};"
        : "+f"(d[0]), "+f"(d[1]), "+f"(d[2]), "+f"(d[3])
        : "r"(a[0]), "r"(a[1]), "r"(a[2]), "r"(a[3]), "r"(b0), "r"(b1));
}

// Swizzle for 32-byte rows (16 bf16): flip 16B-chunk bit by row bit 2.
#define SWZ32(o) ((o) ^ (((o) >> 3) & 0x10))

// ---------------------------------------------------------------------------
// mma.sync GEMM with 3-stage cp.async pipeline.
// C[M,*] = sum_k A[m,k]*B[n,k] + bias[n]   (A:[M,K], B:[N,K])
// A=Ah+Al, B=Bh+Bl (bf16 split), 3 MMA terms. Tile 128x128, BK=16, 8 warps.
// Output split: block-cols < Nsplit -> C0/bias0, else C1/bias1 (col-Nsplit),
// row stride Nout. 48KB static smem, no attribute calls.
// ---------------------------------------------------------------------------
#define MG_STAGE  16384        // Ah(4K) Al(4K) Bh(4K) Bl(4K)

__device__ __forceinline__ void load_stage(uint32_t sstage,
        const __nv_bfloat16* __restrict__ Ah, const __nv_bfloat16* __restrict__ Al,
        const __nv_bfloat16* __restrict__ Bh, const __nv_bfloat16* __restrict__ Bl,
        int arow0, int brow0, int K, int kc, int tid)
{
    const int rr = tid >> 1;          // row 0..127
    const int cp = tid & 1;           // 16B chunk in 32B row
    const uint32_t soff = SWZ32(rr * 32 + cp * 16);
    const size_t ga = (size_t)(arow0 + rr) * K + kc + cp * 8;
    const size_t gb = (size_t)(brow0 + rr) * K + kc + cp * 8;
    cpa16(sstage +         soff, Ah + ga);
    cpa16(sstage + 4096  + soff, Al + ga);
    cpa16(sstage + 8192  + soff, Bh + gb);
    cpa16(sstage + 12288 + soff, Bl + gb);
}

template<int EPI>   // 0: bias, 1: bias + softplus
__global__ __launch_bounds__(256, 2)
void mmagemm(const __nv_bfloat16* __restrict__ Ah, const __nv_bfloat16* __restrict__ Al,
             const __nv_bfloat16* __restrict__ Bh, const __nv_bfloat16* __restrict__ Bl,
             const float* __restrict__ bias0, const float* __restrict__ bias1,
             float* __restrict__ C0, float* __restrict__ C1,
             int Nout, int Nsplit, int K)
{
    __shared__ char smem[3 * MG_STAGE];     // 48 KB static
    const uint32_t sb = smem_u32(smem);
    const int tid  = threadIdx.x;
    const int wid  = tid >> 5;
    const int lane = tid & 31;
    const int warp_m = wid & 1;          // 2 warps in M
    const int warp_n = wid >> 1;         // 4 warps in N
    const int arow0 = blockIdx.y * 128;
    const int brow0 = blockIdx.x * 128;

    // ldmatrix per-lane address components
    const int j = lane >> 3, r = lane & 7;
    const int a_row  = warp_m * 64 + ((j & 1) << 3) + r;   // + mt*16
    const int a_kb16 = (j >> 1) << 4;
    const int b_row  = warp_n * 32 + ((j >> 1) << 3) + r;  // + nt16*16
    const int b_kb16 = (j & 1) << 4;

    float acc[4][4][4];
#pragma unroll
    for (int a = 0; a < 4; a++)
#pragma unroll
        for (int b = 0; b < 4; b++)
#pragma unroll
            for (int c = 0; c < 4; c++) acc[a][b][c] = 0.f;

    const int nch = K >> 4;

    load_stage(sb,            Ah, Al, Bh, Bl, arow0, brow0, K, 0,  tid);
    asm volatile("cp.async.commit_group;");
    load_stage(sb + MG_STAGE, Ah, Al, Bh, Bl, arow0, brow0, K, 16, tid);
    asm volatile("cp.async.commit_group;");

    int stage = 0;
    for (int i = 0; i < nch; i++) {
        if (i + 2 < nch) {
            int ns = stage + 2; if (ns >= 3) ns -= 3;
            load_stage(sb + ns * MG_STAGE, Ah, Al, Bh, Bl,
                       arow0, brow0, K, (i + 2) * 16, tid);
            asm volatile("cp.async.commit_group;");
            asm volatile("cp.async.wait_group 2;");
        } else if (i + 1 < nch) {
            asm volatile("cp.async.wait_group 1;");
        } else {
            asm volatile("cp.async.wait_group 0;");
        }
        __syncthreads();

        const uint32_t st = sb + stage * MG_STAGE;

        uint32_t bh[2][4], bl[2][4];
#pragma unroll
        for (int nt16 = 0; nt16 < 2; nt16++) {
            const uint32_t boff = SWZ32((b_row + nt16 * 16) * 32 + b_kb16);
            ldsm4(st + 8192  + boff, bh[nt16]);
            ldsm4(st + 12288 + boff, bl[nt16]);
        }
#pragma unroll
        for (int mt = 0; mt < 4; mt++) {
            const uint32_t aoff = SWZ32((a_row + mt * 16) * 32 + a_kb16);
            uint32_t ahf[4], alf[4];
            ldsm4(st +        aoff, ahf);
            ldsm4(st + 4096 + aoff, alf);
#pragma unroll
            for (int nt = 0; nt < 4; nt++) {
                const uint32_t b0h = bh[nt >> 1][(nt & 1) * 2];
                const uint32_t b1h = bh[nt >> 1][(nt & 1) * 2 + 1];
                const uint32_t b0l = bl[nt >> 1][(nt & 1) * 2];
                const uint32_t b1l = bl[nt >> 1][(nt & 1) * 2 + 1];
                mma16816(acc[mt][nt], ahf, b0h, b1h);
                mma16816(acc[mt][nt], ahf, b0l, b1l);
                mma16816(acc[mt][nt], alf, b0h, b1h);
            }
        }
        __syncthreads();   // protect stage about to be overwritten
        if (++stage == 3) stage = 0;
    }

    // Epilogue — route to C0 or C1 by block column
    const float* bias = bias0;
    float* Cp = C0;
    int colbase = brow0;
    if (brow0 >= Nsplit) { bias = bias1; Cp = C1; colbase = brow0 - Nsplit; }

    const int gid = lane >> 2, tig = lane & 3;
#pragma unroll
    for (int mt = 0; mt < 4; mt++) {
        const int r0 = arow0 + warp_m * 64 + mt * 16 + gid;
#pragma unroll
        for (int nt = 0; nt < 4; nt++) {
            const int col = colbase + warp_n * 32 + nt * 8 + tig * 2;
            const float bb0 = __ldg(bias + col);
            const float bb1 = __ldg(bias + col + 1);
            float v0 = acc[mt][nt][0] + bb0;
            float v1 = acc[mt][nt][1] + bb1;
            float v2 = acc[mt][nt][2] + bb0;
            float v3 = acc[mt][nt][3] + bb1;
            if (EPI == 1) {
                v0 = (v0 > 20.f) ? v0 : log1pf(expf(v0));
                v1 = (v1 > 20.f) ? v1 : log1pf(expf(v1));
                v2 = (v2 > 20.f) ? v2 : log1pf(expf(v2));
                v3 = (v3 > 20.f) ? v3 : log1pf(expf(v3));
            }
            float2 p01; p01.x = v0; p01.y = v1;
            float2 p23; p23.x = v2; p23.y = v3;
            *(float2*)(Cp + (size_t)r0 * Nout + col)       = p01;
            *(float2*)(Cp + (size_t)(r0 + 8) * Nout + col) = p23;
        }
    }
}

// ---------------------------------------------------------------------------
// Elementwise bf16 split (only used for the input x)
// ---------------------------------------------------------------------------
__global__ __launch_bounds__(256)
void split_bf16(const float* __restrict__ in, __nv_bfloat16* __restrict__ hi,
                __nv_bfloat16* __restrict__ lo, int n4)
{
    const int i = blockIdx.x * 256 + threadIdx.x;
    if (i >= n4) return;
    float4 v = ((const float4*)in)[i];
    float f[4] = {v.x, v.y, v.z, v.w};
    __nv_bfloat16 h[4], l[4];
#pragma unroll
    for (int j = 0; j < 4; j++) {
        h[j] = __float2bfloat16(f[j]);
        l[j] = __float2bfloat16(f[j] - __bfloat162float(h[j]));
    }
    __nv_bfloat162 H0, H1, L0, L1;
    H0.x = h[0]; H0.y = h[1]; H1.x = h[2]; H1.y = h[3];
    L0.x = l[0]; L0.y = l[1]; L1.x = l[2]; L1.y = l[3];
    ((__nv_bfloat162*)hi)[i * 2]     = H0;
    ((__nv_bfloat162*)hi)[i * 2 + 1] = H1;
    ((__nv_bfloat162*)lo)[i * 2]     = L0;
    ((__nv_bfloat162*)lo)[i * 2 + 1] = L1;
}

// ---------------------------------------------------------------------------
// Weight transpose + bf16 split: W[K,N] -> Th[N,K], Tl[N,K] (+row offset)
// ---------------------------------------------------------------------------
__global__ void transpose_split(const float* __restrict__ W, int K, int N,
                                __nv_bfloat16* __restrict__ Th,
                                __nv_bfloat16* __restrict__ Tl)
{
    __shared__ float ts[32][33];
    const int n0 = blockIdx.x * 32, k0 = blockIdx.y * 32;
    const int tx = threadIdx.x, ty = threadIdx.y;
#pragma unroll
    for (int i = 0; i < 4; i++)
        ts[ty + i * 8][tx] = W[(size_t)(k0 + ty + i * 8) * N + n0 + tx];
    __syncthreads();
#pragma unroll
    for (int i = 0; i < 4; i++) {
        float v = ts[tx][ty + i * 8];
        __nv_bfloat16 h = __float2bfloat16(v);
        __nv_bfloat16 l = __float2bfloat16(v - __bfloat162float(h));
        size_t o = (size_t)(n0 + ty + i * 8) * K + k0 + tx;
        Th[o] = h;
        Tl[o] = l;
    }
}

// ---------------------------------------------------------------------------
// Causal depthwise conv (K=4) + bias + silu, fused with bf16 hi/lo split
// ---------------------------------------------------------------------------
__global__ __launch_bounds__(256)
void conv_silu(const float* __restrict__ xz, const float* __restrict__ w,
               const float* __restrict__ cb, float* __restrict__ act,
               __nv_bfloat16* __restrict__ ah, __nv_bfloat16* __restrict__ al)
{
    const int idx = blockIdx.x * 256 + threadIdx.x;
    if (idx >= MTOT * DINNER) return;
    const int d = idx & (DINNER - 1);
    const int bt = idx >> 11;
    const int t = bt & (LSEQ - 1);

    float s = __ldg(cb + d);
#pragma unroll
    for (int k = 0; k < KCONV; k++) {
        const int tt = t - (KCONV - 1) + k;
        if (tt >= 0)
            s = fmaf(__ldg(w + d * KCONV + k), xz[idx + (k - (KCONV - 1)) * DINNER], s);
    }
    const float v = s / (1.f + __expf(-s));
    act[idx] = v;
    const __nv_bfloat16 h = __float2bfloat16(v);
    ah[idx] = h;
    al[idx] = __float2bfloat16(v - __bfloat162float(h));
}

// ---------------------------------------------------------------------------
// Skinny GEMM: Bm = act @ W_B, Cm = act @ W_C
// ---------------------------------------------------------------------------
__global__ __launch_bounds__(256)
void bc_gemm(const float* __restrict__ act,
             const float* __restrict__ WB, const float* __restrict__ WC,
             float* __restrict__ Bm, float* __restrict__ Cm)
{
    const int m = blockIdx.x * 16 + (threadIdx.x >> 4);
    const int n = threadIdx.x & 15;
    const float* a = act + (size_t)m * DINNER;

    float sb = 0.f, sc = 0.f;
#pragma unroll 8
    for (int k = 0; k < DINNER; k++) {
        const float av = a[k];
        sb = fmaf(av, __ldg(WB + k * NSTATE + n), sb);
        sc = fmaf(av, __ldg(WC + k * NSTATE + n), sc);
    }
    Bm[m * NSTATE + n] = sb;
    Cm[m * NSTATE + n] = sc;
}

// ---------------------------------------------------------------------------
// Selective scan + skip + gating, MLP=8, writes gh/gl bf16 split directly
// ---------------------------------------------------------------------------
__global__ __launch_bounds__(256)
void scan_kernel(const float* __restrict__ delta, const float* __restrict__ act,
                 const float* __restrict__ Bm, const float* __restrict__ Cm,
                 const float* __restrict__ A_log, const float* __restrict__ D_skip,
                 const float* __restrict__ xg,
                 __nv_bfloat16* __restrict__ gh, __nv_bfloat16* __restrict__ gl)
{
    const int w = blockIdx.x * 8 + (threadIdx.x >> 5);   // 0 .. 2047
    const int lane = threadIdx.x & 31;
    const int n = lane & 15;
    const int b = w >> 10;
    const int dp = w & 1023;
    const int d = dp * 2 + (lane >> 4);

    const float a = -expf(A_log[d * NSTATE + n]);
    const float dsk = D_skip[d];

    const float* pD = delta + (size_t)b * LSEQ * DINNER + d;
    const float* pX = act   + (size_t)b * LSEQ * DINNER + d;
    const float* pG = xg    + (size_t)b * LSEQ * DINNER + d;
    __nv_bfloat16* pH = gh + (size_t)b * LSEQ * DINNER + d;
    __nv_bfloat16* pL = gl + (size_t)b * LSEQ * DINNER + d;
    const float* pB = Bm + (size_t)b * LSEQ * NSTATE + n;
    const float* pC = Cm + (size_t)b * LSEQ * NSTATE + n;

    float h = 0.f;
    for (int t0 = 0; t0 < LSEQ; t0 += 8) {
        float dv[8], xv[8], gv[8], bv[8], cv[8];
#pragma unroll
        for (int jj = 0; jj < 8; jj++) {
            const size_t o = (size_t)(t0 + jj) * DINNER;
            dv[jj] = pD[o];
            xv[jj] = pX[o];
            gv[jj] = pG[o];
            bv[jj] = pB[(t0 + jj) * NSTATE];
            cv[jj] = pC[(t0 + jj) * NSTATE];
        }
#pragma unroll
        for (int jj = 0; jj < 8; jj++) {
            const float dA = __expf(dv[jj] * a);
            h = fmaf(dA, h, (dv[jj] * xv[jj]) * bv[jj]);
            float p = h * cv[jj];
            p += __shfl_xor_sync(0xffffffffu, p, 1);
            p += __shfl_xor_sync(0xffffffffu, p, 2);
            p += __shfl_xor_sync(0xffffffffu, p, 4);
            p += __shfl_xor_sync(0xffffffffu, p, 8);
            if (n == 0) {
                const float g = gv[jj];
                const float y = (p + xv[jj] * dsk) * (g / (1.f + __expf(-g)));
                const __nv_bfloat16 hh = __float2bfloat16(y);
                pH[(size_t)(t0 + jj) * DINNER] = hh;
                pL[(size_t)(t0 + jj) * DINNER] =
                    __float2bfloat16(y - __bfloat162float(hh));
            }
        }
    }
}

// ---------------------------------------------------------------------------
// Launch
// ---------------------------------------------------------------------------
extern "C" void kernel_launch(void* const* d_in, const int* in_sizes, int n_in,
                              void* d_out, int out_size)
{
    const float* x      = (const float*)d_in[0];
    const float* W_in   = (const float*)d_in[1];
    const float* b_in   = (const float*)d_in[2];
    const float* W_gate = (const float*)d_in[3];
    const float* b_gate = (const float*)d_in[4];
    const float* conv_w = (const float*)d_in[5];
    const float* conv_b = (const float*)d_in[6];
    const float* A_log  = (const float*)d_in[7];
    const float* D_skip = (const float*)d_in[8];
    const float* W_delta= (const float*)d_in[9];
    const float* b_delta= (const float*)d_in[10];
    const float* W_B    = (const float*)d_in[11];
    const float* W_C    = (const float*)d_in[12];
    const float* W_out  = (const float*)d_in[13];
    const float* b_out  = (const float*)d_in[14];
    float* out = (float*)d_out;

    float *xz, *xg, *act, *delt, *Bm, *Cm;
    cudaGetSymbolAddress((void**)&xz,    g_xz);
    cudaGetSymbolAddress((void**)&xg,    g_xg);
    cudaGetSymbolAddress((void**)&act,   g_act);
    cudaGetSymbolAddress((void**)&delt,  g_delta);
    cudaGetSymbolAddress((void**)&Bm,    g_Bm);
    cudaGetSymbolAddress((void**)&Cm,    g_Cm);

    __nv_bfloat16 *xh, *xl, *ah, *al, *gh, *gl, *wth, *wtl;
    cudaGetSymbolAddress((void**)&xh,  g_xh);
    cudaGetSymbolAddress((void**)&xl,  g_xl);
    cudaGetSymbolAddress((void**)&ah,  g_ah);
    cudaGetSymbolAddress((void**)&al,  g_al);
    cudaGetSymbolAddress((void**)&gh,  g_gh);
    cudaGetSymbolAddress((void**)&gl,  g_gl);
    cudaGetSymbolAddress((void**)&wth, g_wth);
    cudaGetSymbolAddress((void**)&wtl, g_wtl);

    // 0) split x -> bf16 hi/lo
    {
        const int n4 = MTOT * DMODEL / 4;
        split_bf16<<<(n4 + 255) / 256, 256>>>(x, xh, xl, n4);
    }
    // 1) fused in+gate: [xz | xg] = x @ [W_in | W_gate] + [b_in | b_gate]
    //    weights transposed into wth rows 0..2047 (in) and 2048..4095 (gate)
    {
        dim3 tg(DINNER / 32, DMODEL / 32);
        transpose_split<<<tg, dim3(32, 8)>>>(W_in,   DMODEL, DINNER, wth, wtl);
        transpose_split<<<tg, dim3(32, 8)>>>(W_gate, DMODEL, DINNER,
                                             wth + (size_t)DINNER * DMODEL,
                                             wtl + (size_t)DINNER * DMODEL);
        dim3 grid(2 * DINNER / 128, MTOT / 128);     // 32 x 32
        mmagemm<0><<<grid, 256>>>(xh, xl, wth, wtl, b_in, b_gate,
                                  xz, xg, DINNER, DINNER, DMODEL);
    }
    // 2) act = silu(conv(xz) + conv_b)  (+ bf16 split -> ah/al)
    {
        const int total = MTOT * DINNER;
        conv_silu<<<(total + 255) / 256, 256>>>(xz, conv_w, conv_b, act, ah, al);
    }
    // 3) delta = softplus(act @ W_delta + b_delta)
    {
        dim3 tg(DINNER / 32, DINNER / 32);
        transpose_split<<<tg, dim3(32, 8)>>>(W_delta, DINNER, DINNER, wth, wtl);
        dim3 grid(DINNER / 128, MTOT / 128);
        mmagemm<1><<<grid, 256>>>(ah, al, wth, wtl, b_delta, b_delta,
                                  delt, delt, DINNER, DINNER, DINNER);
    }
    // 4) Bm, Cm
    {
        bc_gemm<<<MTOT / 16, 256>>>(act, W_B, W_C, Bm, Cm);
    }
    // 5) scan + skip + gating -> gh/gl (bf16 split)
    {
        scan_kernel<<<(BATCH * DINNER / 2) / 8, 256>>>(delt, act, Bm, Cm,
                                                       A_log, D_skip, xg, gh, gl);
    }
    // 6) out = gated @ W_out + b_out
    {
        dim3 tg(DMODEL / 32, DINNER / 32);
        transpose_split<<<tg, dim3(32, 8)>>>(W_out, DINNER, DMODEL, wth, wtl);
        dim3 grid(DMODEL / 128, MTOT / 128);
        mmagemm<0><<<grid, 256>>>(gh, gl, wth, wtl, b_out, b_out,
                                  out, out, DMODEL, DMODEL, DINNER);
    }
}

// round 12
// speedup vs baseline: 2.6136x; 1.0115x over previous
#include <cuda_runtime.h>
#include <cuda_bf16.h>
#include <math.h>
#include <stdint.h>

// Problem constants
#define BATCH   2
#define LSEQ    2048
#define DMODEL  1024
#define DINNER  2048
#define NSTATE  16
#define KCONV   4
#define MTOT    (BATCH * LSEQ)      // 4096

// ---------------------------------------------------------------------------
// Static scratch (no allocations allowed)
// ---------------------------------------------------------------------------
__device__ float g_xz[MTOT * DINNER];
__device__ float g_xg[MTOT * DINNER];
__device__ float g_act[MTOT * DINNER];
__device__ float g_delta[MTOT * DINNER];
__device__ float g_Bm[MTOT * NSTATE];
__device__ float g_Cm[MTOT * NSTATE];

// bf16 split operands
__device__ __nv_bfloat16 g_xh[MTOT * DMODEL];
__device__ __nv_bfloat16 g_xl[MTOT * DMODEL];
__device__ __nv_bfloat16 g_ah[MTOT * DINNER];
__device__ __nv_bfloat16 g_al[MTOT * DINNER];
__device__ __nv_bfloat16 g_gh[MTOT * DINNER];
__device__ __nv_bfloat16 g_gl[MTOT * DINNER];
// transposed weight buffer (4096x1024 for fused in+gate; reused for others)
__device__ __nv_bfloat16 g_wth[DINNER * DINNER];
__device__ __nv_bfloat16 g_wtl[DINNER * DINNER];

// ---------------------------------------------------------------------------
// PTX helpers — sm_80-class path (ldmatrix / mma.sync / cp.async)
// ---------------------------------------------------------------------------
__device__ __forceinline__ uint32_t smem_u32(const void* p) {
    uint32_t a;
    asm("{ .reg .u64 t; cvta.to.shared.u64 t, %1; cvt.u32.u64 %0, t; }"
        : "=r"(a) : "l"(p));
    return a;
}
__device__ __forceinline__ void cpa16(uint32_t dst, const void* src) {
    asm volatile("cp.async.cg.shared.global [%0], [%1], 16;"
                 :: "r"(dst), "l"(src));
}
__device__ __forceinline__ void ldsm4(uint32_t addr, uint32_t* q) {
    asm volatile("ldmatrix.sync.aligned.m8n8.x4.shared.b16 {%0,%1,%2,%3}, [%4];"
                 : "=r"(q[0]), "=r"(q[1]), "=r"(q[2]), "=r"(q[3]) : "r"(addr));
}
__device__ __forceinline__ void mma16816(float* d, const uint32_t* a,
                                         uint32_t b0, uint32_t b1) {
    asm volatile(
        "mma.sync.aligned.m16n8k16.row.col.f32.bf16.bf16.f32 "
        "{%0,%1,%2,%3}, {%4,%5,%6,%7}, {%8,%9}, {%0,%1,%2,%3};"
        : "+f"(d[0]), "+f"(d[1]), "+f"(d[2]), "+f"(d[3])
        : "r"(a[0]), "r"(a[1]), "r"(a[2]), "r"(a[3]), "r"(b0), "r"(b1));
}

// Swizzle for 32-byte rows (16 bf16): flip 16B-chunk bit by row bit 2.
#define SWZ32(o) ((o) ^ (((o) >> 3) & 0x10))

// ---------------------------------------------------------------------------
// mma.sync GEMM, 3-stage cp.async pipeline, ONE barrier per chunk.
// C[M,*] = sum_k A[m,k]*B[n,k] + bias[n]   (A:[M,K], B:[N,K])
// A=Ah+Al, B=Bh+Bl (bf16 split), 3 MMA terms. Tile 128x128, BK=16, 8 warps.
// Output split: block-cols < Nsplit -> C0/bias0, else C1/bias1 (col-Nsplit),
// row stride Nout. 48KB static smem, no attribute calls.
//
// Loop structure (WAR-safe single sync):
//   wait_group(i+1<nch ? 1 : 0)   -> chunk i complete (this thread)
//   __syncthreads()               -> chunk i visible to all; all warps past
//                                    compute(i-1), so stage (i+2)%3 is free
//   cp.async chunk i+2            -> overlaps compute below
//   compute chunk i
// ---------------------------------------------------------------------------
#define MG_STAGE  16384        // Ah(4K) Al(4K) Bh(4K) Bl(4K)

__device__ __forceinline__ void load_stage(uint32_t sstage,
        const __nv_bfloat16* __restrict__ Ah, const __nv_bfloat16* __restrict__ Al,
        const __nv_bfloat16* __restrict__ Bh, const __nv_bfloat16* __restrict__ Bl,
        int arow0, int brow0, int K, int kc, int tid)
{
    const int rr = tid >> 1;          // row 0..127
    const int cp = tid & 1;           // 16B chunk in 32B row
    const uint32_t soff = SWZ32(rr * 32 + cp * 16);
    const size_t ga = (size_t)(arow0 + rr) * K + kc + cp * 8;
    const size_t gb = (size_t)(brow0 + rr) * K + kc + cp * 8;
    cpa16(sstage +         soff, Ah + ga);
    cpa16(sstage + 4096  + soff, Al + ga);
    cpa16(sstage + 8192  + soff, Bh + gb);
    cpa16(sstage + 12288 + soff, Bl + gb);
}

template<int EPI>   // 0: bias, 1: bias + softplus
__global__ __launch_bounds__(256, 2)
void mmagemm(const __nv_bfloat16* __restrict__ Ah, const __nv_bfloat16* __restrict__ Al,
             const __nv_bfloat16* __restrict__ Bh, const __nv_bfloat16* __restrict__ Bl,
             const float* __restrict__ bias0, const float* __restrict__ bias1,
             float* __restrict__ C0, float* __restrict__ C1,
             int Nout, int Nsplit, int K)
{
    __shared__ char smem[3 * MG_STAGE];     // 48 KB static
    const uint32_t sb = smem_u32(smem);
    const int tid  = threadIdx.x;
    const int wid  = tid >> 5;
    const int lane = tid & 31;
    const int warp_m = wid & 1;          // 2 warps in M
    const int warp_n = wid >> 1;         // 4 warps in N
    const int arow0 = blockIdx.y * 128;
    const int brow0 = blockIdx.x * 128;

    // ldmatrix per-lane address components
    const int j = lane >> 3, r = lane & 7;
    const int a_row  = warp_m * 64 + ((j & 1) << 3) + r;   // + mt*16
    const int a_kb16 = (j >> 1) << 4;
    const int b_row  = warp_n * 32 + ((j >> 1) << 3) + r;  // + nt16*16
    const int b_kb16 = (j & 1) << 4;

    float acc[4][4][4];
#pragma unroll
    for (int a = 0; a < 4; a++)
#pragma unroll
        for (int b = 0; b < 4; b++)
#pragma unroll
            for (int c = 0; c < 4; c++) acc[a][b][c] = 0.f;

    const int nch = K >> 4;   // >= 64 for all our shapes

    load_stage(sb,            Ah, Al, Bh, Bl, arow0, brow0, K, 0,  tid);
    asm volatile("cp.async.commit_group;");
    load_stage(sb + MG_STAGE, Ah, Al, Bh, Bl, arow0, brow0, K, 16, tid);
    asm volatile("cp.async.commit_group;");

    int stage = 0;
    for (int i = 0; i < nch; i++) {
        if (i + 1 < nch) {
            asm volatile("cp.async.wait_group 1;");
        } else {
            asm volatile("cp.async.wait_group 0;");
        }
        __syncthreads();

        // Issue next-next chunk load; overlaps compute of chunk i.
        if (i + 2 < nch) {
            int ns = stage + 2; if (ns >= 3) ns -= 3;
            load_stage(sb + ns * MG_STAGE, Ah, Al, Bh, Bl,
                       arow0, brow0, K, (i + 2) * 16, tid);
            asm volatile("cp.async.commit_group;");
        }

        const uint32_t st = sb + stage * MG_STAGE;

        uint32_t bh[2][4], bl[2][4];
#pragma unroll
        for (int nt16 = 0; nt16 < 2; nt16++) {
            const uint32_t boff = SWZ32((b_row + nt16 * 16) * 32 + b_kb16);
            ldsm4(st + 8192  + boff, bh[nt16]);
            ldsm4(st + 12288 + boff, bl[nt16]);
        }
#pragma unroll
        for (int mt = 0; mt < 4; mt++) {
            const uint32_t aoff = SWZ32((a_row + mt * 16) * 32 + a_kb16);
            uint32_t ahf[4], alf[4];
            ldsm4(st +        aoff, ahf);
            ldsm4(st + 4096 + aoff, alf);
#pragma unroll
            for (int nt = 0; nt < 4; nt++) {
                const uint32_t b0h = bh[nt >> 1][(nt & 1) * 2];
                const uint32_t b1h = bh[nt >> 1][(nt & 1) * 2 + 1];
                const uint32_t b0l = bl[nt >> 1][(nt & 1) * 2];
                const uint32_t b1l = bl[nt >> 1][(nt & 1) * 2 + 1];
                mma16816(acc[mt][nt], ahf, b0h, b1h);
                mma16816(acc[mt][nt], ahf, b0l, b1l);
                mma16816(acc[mt][nt], alf, b0h, b1h);
            }
        }
        if (++stage == 3) stage = 0;
    }

    // Epilogue — route to C0 or C1 by block column
    const float* bias = bias0;
    float* Cp = C0;
    int colbase = brow0;
    if (brow0 >= Nsplit) { bias = bias1; Cp = C1; colbase = brow0 - Nsplit; }

    const int gid = lane >> 2, tig = lane & 3;
#pragma unroll
    for (int mt = 0; mt < 4; mt++) {
        const int r0 = arow0 + warp_m * 64 + mt * 16 + gid;
#pragma unroll
        for (int nt = 0; nt < 4; nt++) {
            const int col = colbase + warp_n * 32 + nt * 8 + tig * 2;
            const float bb0 = __ldg(bias + col);
            const float bb1 = __ldg(bias + col + 1);
            float v0 = acc[mt][nt][0] + bb0;
            float v1 = acc[mt][nt][1] + bb1;
            float v2 = acc[mt][nt][2] + bb0;
            float v3 = acc[mt][nt][3] + bb1;
            if (EPI == 1) {
                v0 = (v0 > 20.f) ? v0 : log1pf(expf(v0));
                v1 = (v1 > 20.f) ? v1 : log1pf(expf(v1));
                v2 = (v2 > 20.f) ? v2 : log1pf(expf(v2));
                v3 = (v3 > 20.f) ? v3 : log1pf(expf(v3));
            }
            float2 p01; p01.x = v0; p01.y = v1;
            float2 p23; p23.x = v2; p23.y = v3;
            *(float2*)(Cp + (size_t)r0 * Nout + col)       = p01;
            *(float2*)(Cp + (size_t)(r0 + 8) * Nout + col) = p23;
        }
    }
}

// ---------------------------------------------------------------------------
// Elementwise bf16 split (only used for the input x)
// ---------------------------------------------------------------------------
__global__ __launch_bounds__(256)
void split_bf16(const float* __restrict__ in, __nv_bfloat16* __restrict__ hi,
                __nv_bfloat16* __restrict__ lo, int n4)
{
    const int i = blockIdx.x * 256 + threadIdx.x;
    if (i >= n4) return;
    float4 v = ((const float4*)in)[i];
    float f[4] = {v.x, v.y, v.z, v.w};
    __nv_bfloat16 h[4], l[4];
#pragma unroll
    for (int j = 0; j < 4; j++) {
        h[j] = __float2bfloat16(f[j]);
        l[j] = __float2bfloat16(f[j] - __bfloat162float(h[j]));
    }
    __nv_bfloat162 H0, H1, L0, L1;
    H0.x = h[0]; H0.y = h[1]; H1.x = h[2]; H1.y = h[3];
    L0.x = l[0]; L0.y = l[1]; L1.x = l[2]; L1.y = l[3];
    ((__nv_bfloat162*)hi)[i * 2]     = H0;
    ((__nv_bfloat162*)hi)[i * 2 + 1] = H1;
    ((__nv_bfloat162*)lo)[i * 2]     = L0;
    ((__nv_bfloat162*)lo)[i * 2 + 1] = L1;
}

// ---------------------------------------------------------------------------
// Weight transpose + bf16 split: W[K,N] -> Th[N,K], Tl[N,K]
// ---------------------------------------------------------------------------
__global__ void transpose_split(const float* __restrict__ W, int K, int N,
                                __nv_bfloat16* __restrict__ Th,
                                __nv_bfloat16* __restrict__ Tl)
{
    __shared__ float ts[32][33];
    const int n0 = blockIdx.x * 32, k0 = blockIdx.y * 32;
    const int tx = threadIdx.x, ty = threadIdx.y;
#pragma unroll
    for (int i = 0; i < 4; i++)
        ts[ty + i * 8][tx] = W[(size_t)(k0 + ty + i * 8) * N + n0 + tx];
    __syncthreads();
#pragma unroll
    for (int i = 0; i < 4; i++) {
        float v = ts[tx][ty + i * 8];
        __nv_bfloat16 h = __float2bfloat16(v);
        __nv_bfloat16 l = __float2bfloat16(v - __bfloat162float(h));
        size_t o = (size_t)(n0 + ty + i * 8) * K + k0 + tx;
        Th[o] = h;
        Tl[o] = l;
    }
}

// ---------------------------------------------------------------------------
// Causal depthwise conv (K=4) + bias + silu, fused with bf16 hi/lo split
// ---------------------------------------------------------------------------
__global__ __launch_bounds__(256)
void conv_silu(const float* __restrict__ xz, const float* __restrict__ w,
               const float* __restrict__ cb, float* __restrict__ act,
               __nv_bfloat16* __restrict__ ah, __nv_bfloat16* __restrict__ al)
{
    const int idx = blockIdx.x * 256 + threadIdx.x;
    if (idx >= MTOT * DINNER) return;
    const int d = idx & (DINNER - 1);
    const int bt = idx >> 11;
    const int t = bt & (LSEQ - 1);

    float s = __ldg(cb + d);
#pragma unroll
    for (int k = 0; k < KCONV; k++) {
        const int tt = t - (KCONV - 1) + k;
        if (tt >= 0)
            s = fmaf(__ldg(w + d * KCONV + k), xz[idx + (k - (KCONV - 1)) * DINNER], s);
    }
    const float v = s / (1.f + __expf(-s));
    act[idx] = v;
    const __nv_bfloat16 h = __float2bfloat16(v);
    ah[idx] = h;
    al[idx] = __float2bfloat16(v - __bfloat162float(h));
}

// ---------------------------------------------------------------------------
// Skinny GEMM: Bm = act @ W_B, Cm = act @ W_C
// ---------------------------------------------------------------------------
__global__ __launch_bounds__(256)
void bc_gemm(const float* __restrict__ act,
             const float* __restrict__ WB, const float* __restrict__ WC,
             float* __restrict__ Bm, float* __restrict__ Cm)
{
    const int m = blockIdx.x * 16 + (threadIdx.x >> 4);
    const int n = threadIdx.x & 15;
    const float* a = act + (size_t)m * DINNER;

    float sb = 0.f, sc = 0.f;
#pragma unroll 8
    for (int k = 0; k < DINNER; k++) {
        const float av = a[k];
        sb = fmaf(av, __ldg(WB + k * NSTATE + n), sb);
        sc = fmaf(av, __ldg(WC + k * NSTATE + n), sc);
    }
    Bm[m * NSTATE + n] = sb;
    Cm[m * NSTATE + n] = sc;
}

// ---------------------------------------------------------------------------
// Selective scan + skip + gating, MLP=8, writes gh/gl bf16 split directly
// ---------------------------------------------------------------------------
__global__ __launch_bounds__(256)
void scan_kernel(const float* __restrict__ delta, const float* __restrict__ act,
                 const float* __restrict__ Bm, const float* __restrict__ Cm,
                 const float* __restrict__ A_log, const float* __restrict__ D_skip,
                 const float* __restrict__ xg,
                 __nv_bfloat16* __restrict__ gh, __nv_bfloat16* __restrict__ gl)
{
    const int w = blockIdx.x * 8 + (threadIdx.x >> 5);   // 0 .. 2047
    const int lane = threadIdx.x & 31;
    const int n = lane & 15;
    const int b = w >> 10;
    const int dp = w & 1023;
    const int d = dp * 2 + (lane >> 4);

    const float a = -expf(A_log[d * NSTATE + n]);
    const float dsk = D_skip[d];

    const float* pD = delta + (size_t)b * LSEQ * DINNER + d;
    const float* pX = act   + (size_t)b * LSEQ * DINNER + d;
    const float* pG = xg    + (size_t)b * LSEQ * DINNER + d;
    __nv_bfloat16* pH = gh + (size_t)b * LSEQ * DINNER + d;
    __nv_bfloat16* pL = gl + (size_t)b * LSEQ * DINNER + d;
    const float* pB = Bm + (size_t)b * LSEQ * NSTATE + n;
    const float* pC = Cm + (size_t)b * LSEQ * NSTATE + n;

    float h = 0.f;
    for (int t0 = 0; t0 < LSEQ; t0 += 8) {
        float dv[8], xv[8], gv[8], bv[8], cv[8];
#pragma unroll
        for (int jj = 0; jj < 8; jj++) {
            const size_t o = (size_t)(t0 + jj) * DINNER;
            dv[jj] = pD[o];
            xv[jj] = pX[o];
            gv[jj] = pG[o];
            bv[jj] = pB[(t0 + jj) * NSTATE];
            cv[jj] = pC[(t0 + jj) * NSTATE];
        }
#pragma unroll
        for (int jj = 0; jj < 8; jj++) {
            const float dA = __expf(dv[jj] * a);
            h = fmaf(dA, h, (dv[jj] * xv[jj]) * bv[jj]);
            float p = h * cv[jj];
            p += __shfl_xor_sync(0xffffffffu, p, 1);
            p += __shfl_xor_sync(0xffffffffu, p, 2);
            p += __shfl_xor_sync(0xffffffffu, p, 4);
            p += __shfl_xor_sync(0xffffffffu, p, 8);
            if (n == 0) {
                const float g = gv[jj];
                const float y = (p + xv[jj] * dsk) * (g / (1.f + __expf(-g)));
                const __nv_bfloat16 hh = __float2bfloat16(y);
                pH[(size_t)(t0 + jj) * DINNER] = hh;
                pL[(size_t)(t0 + jj) * DINNER] =
                    __float2bfloat16(y - __bfloat162float(hh));
            }
        }
    }
}

// ---------------------------------------------------------------------------
// Launch
// ---------------------------------------------------------------------------
extern "C" void kernel_launch(void* const* d_in, const int* in_sizes, int n_in,
                              void* d_out, int out_size)
{
    const float* x      = (const float*)d_in[0];
    const float* W_in   = (const float*)d_in[1];
    const float* b_in   = (const float*)d_in[2];
    const float* W_gate = (const float*)d_in[3];
    const float* b_gate = (const float*)d_in[4];
    const float* conv_w = (const float*)d_in[5];
    const float* conv_b = (const float*)d_in[6];
    const float* A_log  = (const float*)d_in[7];
    const float* D_skip = (const float*)d_in[8];
    const float* W_delta= (const float*)d_in[9];
    const float* b_delta= (const float*)d_in[10];
    const float* W_B    = (const float*)d_in[11];
    const float* W_C    = (const float*)d_in[12];
    const float* W_out  = (const float*)d_in[13];
    const float* b_out  = (const float*)d_in[14];
    float* out = (float*)d_out;

    float *xz, *xg, *act, *delt, *Bm, *Cm;
    cudaGetSymbolAddress((void**)&xz,    g_xz);
    cudaGetSymbolAddress((void**)&xg,    g_xg);
    cudaGetSymbolAddress((void**)&act,   g_act);
    cudaGetSymbolAddress((void**)&delt,  g_delta);
    cudaGetSymbolAddress((void**)&Bm,    g_Bm);
    cudaGetSymbolAddress((void**)&Cm,    g_Cm);

    __nv_bfloat16 *xh, *xl, *ah, *al, *gh, *gl, *wth, *wtl;
    cudaGetSymbolAddress((void**)&xh,  g_xh);
    cudaGetSymbolAddress((void**)&xl,  g_xl);
    cudaGetSymbolAddress((void**)&ah,  g_ah);
    cudaGetSymbolAddress((void**)&al,  g_al);
    cudaGetSymbolAddress((void**)&gh,  g_gh);
    cudaGetSymbolAddress((void**)&gl,  g_gl);
    cudaGetSymbolAddress((void**)&wth, g_wth);
    cudaGetSymbolAddress((void**)&wtl, g_wtl);

    // 0) split x -> bf16 hi/lo
    {
        const int n4 = MTOT * DMODEL / 4;
        split_bf16<<<(n4 + 255) / 256, 256>>>(x, xh, xl, n4);
    }
    // 1) fused in+gate: [xz | xg] = x @ [W_in | W_gate] + [b_in | b_gate]
    {
        dim3 tg(DINNER / 32, DMODEL / 32);
        transpose_split<<<tg, dim3(32, 8)>>>(W_in,   DMODEL, DINNER, wth, wtl);
        transpose_split<<<tg, dim3(32, 8)>>>(W_gate, DMODEL, DINNER,
                                             wth + (size_t)DINNER * DMODEL,
                                             wtl + (size_t)DINNER * DMODEL);
        dim3 grid(2 * DINNER / 128, MTOT / 128);     // 32 x 32
        mmagemm<0><<<grid, 256>>>(xh, xl, wth, wtl, b_in, b_gate,
                                  xz, xg, DINNER, DINNER, DMODEL);
    }
    // 2) act = silu(conv(xz) + conv_b)  (+ bf16 split -> ah/al)
    {
        const int total = MTOT * DINNER;
        conv_silu<<<(total + 255) / 256, 256>>>(xz, conv_w, conv_b, act, ah, al);
    }
    // 3) delta = softplus(act @ W_delta + b_delta)
    {
        dim3 tg(DINNER / 32, DINNER / 32);
        transpose_split<<<tg, dim3(32, 8)>>>(W_delta, DINNER, DINNER, wth, wtl);
        dim3 grid(DINNER / 128, MTOT / 128);
        mmagemm<1><<<grid, 256>>>(ah, al, wth, wtl, b_delta, b_delta,
                                  delt, delt, DINNER, DINNER, DINNER);
    }
    // 4) Bm, Cm
    {
        bc_gemm<<<MTOT / 16, 256>>>(act, W_B, W_C, Bm, Cm);
    }
    // 5) scan + skip + gating -> gh/gl (bf16 split)
    {
        scan_kernel<<<(BATCH * DINNER / 2) / 8, 256>>>(delt, act, Bm, Cm,
                                                       A_log, D_skip, xg, gh, gl);
    }
    // 6) out = gated @ W_out + b_out
    {
        dim3 tg(DMODEL / 32, DINNER / 32);
        transpose_split<<<tg, dim3(32, 8)>>>(W_out, DINNER, DMODEL, wth, wtl);
        dim3 grid(DMODEL / 128, MTOT / 128);
        mmagemm<0><<<grid, 256>>>(gh, gl, wth, wtl, b_out, b_out,
                                  out, out, DMODEL, DMODEL, DINNER);
    }
}

// round 13
// speedup vs baseline: 3.0750x; 1.1766x over previous
#include <cuda_runtime.h>
#include <cuda_bf16.h>
#include <math.h>
#include <stdint.h>

// Problem constants
#define BATCH   2
#define LSEQ    2048
#define DMODEL  1024
#define DINNER  2048
#define NSTATE  16
#define KCONV   4
#define MTOT    (BATCH * LSEQ)      // 4096

// ---------------------------------------------------------------------------
// Static scratch
// ---------------------------------------------------------------------------
__device__ float g_xz[MTOT * DINNER];
__device__ float g_xg[MTOT * DINNER];
__device__ float g_act[MTOT * DINNER];
__device__ float g_delta[MTOT * DINNER];
__device__ float g_Bm[MTOT * NSTATE];
__device__ float g_Cm[MTOT * NSTATE];

// tf32-rounded fp32 GEMM operands
__device__ float g_xt[MTOT * DMODEL];      // rounded x
__device__ float g_at[MTOT * DINNER];      // rounded act
__device__ float g_gt[MTOT * DINNER];      // rounded gated
__device__ float g_wt[DINNER * DINNER];    // rounded transposed weights (reused)

// ---------------------------------------------------------------------------
// PTX helpers
// ---------------------------------------------------------------------------
__device__ __forceinline__ uint32_t smem_u32(const void* p) {
    uint32_t a;
    asm("{ .reg .u64 t; cvta.to.shared.u64 t, %1; cvt.u32.u64 %0, t; }"
        : "=r"(a) : "l"(p));
    return a;
}
__device__ __forceinline__ void cpa16(uint32_t dst, const void* src) {
    asm volatile("cp.async.cg.shared.global [%0], [%1], 16;"
                 :: "r"(dst), "l"(src));
}
__device__ __forceinline__ uint32_t lds32(uint32_t addr) {
    uint32_t v;
    asm volatile("ld.shared.b32 %0, [%1];" : "=r"(v) : "r"(addr));
    return v;
}
__device__ __forceinline__ float to_tf32(float f) {
    uint32_t o, i = __float_as_uint(f);
    asm("cvt.rna.tf32.f32 %0, %1;" : "=r"(o) : "r"(i));
    return __uint_as_float(o);
}
__device__ __forceinline__ void mma_tf32(float* d, const uint32_t* a,
                                         uint32_t b0, uint32_t b1) {
    asm volatile(
        "mma.sync.aligned.m16n8k8.row.col.f32.tf32.tf32.f32 "
        "{%0,%1,%2,%3}, {%4,%5,%6,%7}, {%8,%9}, {%0,%1,%2,%3};"
        : "+f"(d[0]), "+f"(d[1]), "+f"(d[2]), "+f"(d[3])
        : "r"(a[0]), "r"(a[1]), "r"(a[2]), "r"(a[3]), "r"(b0), "r"(b1));
}

// ---------------------------------------------------------------------------
// tf32 mma.sync GEMM, 3-stage cp.async pipeline, one barrier per chunk.
// C[M,*] = sum_k A[m,k]*B[n,k] + bias[n]   (A:[M,K], B:[N,K], fp32 tf32-valued)
// Tile 128x128, BK=16 (2 tf32 k-steps), 8 warps (2x4), warp tile 64x32.
// Smem tile: 128 rows x 16 fp32 (64B rows), swizzle: 16B chunk c4 ^= (row>>1)&3.
// Fragment loads conflict-free (bank-verified). 48KB static smem.
// ---------------------------------------------------------------------------
#define MG_STAGE  16384        // A(8K) + B(8K)

__device__ __forceinline__ void load_stage(uint32_t sstage,
        const float* __restrict__ A, const float* __restrict__ B,
        int arow0, int brow0, int K, int kc, int tid)
{
#pragma unroll
    for (int it = 0; it < 2; it++) {
        const int idx = tid + 256 * it;      // 0..511
        const int rr  = idx >> 2;            // row 0..127
        const int c4  = idx & 3;             // 16B chunk
        const uint32_t soff = rr * 64 + ((c4 ^ ((rr >> 1) & 3)) << 4);
        cpa16(sstage +        soff, A + (size_t)(arow0 + rr) * K + kc + c4 * 4);
        cpa16(sstage + 8192 + soff, B + (size_t)(brow0 + rr) * K + kc + c4 * 4);
    }
}

template<int EPI>   // 0: bias, 1: bias + softplus
__global__ __launch_bounds__(256, 2)
void mmagemm(const float* __restrict__ A, const float* __restrict__ B,
             const float* __restrict__ bias0, const float* __restrict__ bias1,
             float* __restrict__ C0, float* __restrict__ C1,
             int Nout, int Nsplit, int K)
{
    __shared__ char smem[3 * MG_STAGE];     // 48 KB static
    const uint32_t sb = smem_u32(smem);
    const int tid  = threadIdx.x;
    const int wid  = tid >> 5;
    const int lane = tid & 31;
    const int warp_m = wid & 1;
    const int warp_n = wid >> 1;
    const int arow0 = blockIdx.y * 128;
    const int brow0 = blockIdx.x * 128;

    // per-lane fragment address constants
    const int rA = lane >> 2;                 // 0..7
    const int cA = lane & 3;                  // 0..3
    const int swz = ((rA >> 1) & 3) << 2;     // swizzle in float units
    uint32_t kx[2], kx4[2];
#pragma unroll
    for (int s = 0; s < 2; s++) {
        kx[s]  = (uint32_t)(((s * 8 + cA)     ^ swz) << 2);
        kx4[s] = (uint32_t)(((s * 8 + cA + 4) ^ swz) << 2);
    }
    const int m0 = warp_m * 64;
    const int n0 = warp_n * 32;

    float acc[4][4][4];
#pragma unroll
    for (int a = 0; a < 4; a++)
#pragma unroll
        for (int b = 0; b < 4; b++)
#pragma unroll
            for (int c = 0; c < 4; c++) acc[a][b][c] = 0.f;

    const int nch = K >> 4;

    load_stage(sb,            A, B, arow0, brow0, K, 0,  tid);
    asm volatile("cp.async.commit_group;");
    load_stage(sb + MG_STAGE, A, B, arow0, brow0, K, 16, tid);
    asm volatile("cp.async.commit_group;");

    int stage = 0;
    for (int i = 0; i < nch; i++) {
        if (i + 1 < nch) {
            asm volatile("cp.async.wait_group 1;");
        } else {
            asm volatile("cp.async.wait_group 0;");
        }
        __syncthreads();

        if (i + 2 < nch) {
            int ns = stage + 2; if (ns >= 3) ns -= 3;
            load_stage(sb + ns * MG_STAGE, A, B, arow0, brow0, K, (i + 2) * 16, tid);
            asm volatile("cp.async.commit_group;");
        }

        const uint32_t st = sb + stage * MG_STAGE;
#pragma unroll
        for (int ks = 0; ks < 2; ks++) {
            uint32_t bf[4][2];
#pragma unroll
            for (int nt = 0; nt < 4; nt++) {
                const uint32_t rb = st + 8192 + (n0 + nt * 8 + rA) * 64;
                bf[nt][0] = lds32(rb + kx[ks]);
                bf[nt][1] = lds32(rb + kx4[ks]);
            }
#pragma unroll
            for (int mt = 0; mt < 4; mt++) {
                const uint32_t ra = st + (m0 + mt * 16 + rA) * 64;
                uint32_t af[4];
                af[0] = lds32(ra +       kx[ks]);
                af[1] = lds32(ra + 512 + kx[ks]);
                af[2] = lds32(ra +       kx4[ks]);
                af[3] = lds32(ra + 512 + kx4[ks]);
#pragma unroll
                for (int nt = 0; nt < 4; nt++)
                    mma_tf32(acc[mt][nt], af, bf[nt][0], bf[nt][1]);
            }
        }
        if (++stage == 3) stage = 0;
    }

    // Epilogue — route to C0 or C1 by block column
    const float* bias = bias0;
    float* Cp = C0;
    int colbase = brow0;
    if (brow0 >= Nsplit) { bias = bias1; Cp = C1; colbase = brow0 - Nsplit; }

    const int gid = lane >> 2, tig = lane & 3;
#pragma unroll
    for (int mt = 0; mt < 4; mt++) {
        const int r0 = arow0 + m0 + mt * 16 + gid;
#pragma unroll
        for (int nt = 0; nt < 4; nt++) {
            const int col = colbase + n0 + nt * 8 + tig * 2;
            const float bb0 = __ldg(bias + col);
            const float bb1 = __ldg(bias + col + 1);
            float v0 = acc[mt][nt][0] + bb0;
            float v1 = acc[mt][nt][1] + bb1;
            float v2 = acc[mt][nt][2] + bb0;
            float v3 = acc[mt][nt][3] + bb1;
            if (EPI == 1) {
                v0 = (v0 > 20.f) ? v0 : log1pf(expf(v0));
                v1 = (v1 > 20.f) ? v1 : log1pf(expf(v1));
                v2 = (v2 > 20.f) ? v2 : log1pf(expf(v2));
                v3 = (v3 > 20.f) ? v3 : log1pf(expf(v3));
            }
            float2 p01; p01.x = v0; p01.y = v1;
            float2 p23; p23.x = v2; p23.y = v3;
            *(float2*)(Cp + (size_t)r0 * Nout + col)       = p01;
            *(float2*)(Cp + (size_t)(r0 + 8) * Nout + col) = p23;
        }
    }
}

// ---------------------------------------------------------------------------
// Elementwise tf32 rounding (for input x)
// ---------------------------------------------------------------------------
__global__ __launch_bounds__(256)
void round_tf32(const float* __restrict__ in, float* __restrict__ out, int n4)
{
    const int i = blockIdx.x * 256 + threadIdx.x;
    if (i >= n4) return;
    float4 v = ((const float4*)in)[i];
    v.x = to_tf32(v.x); v.y = to_tf32(v.y);
    v.z = to_tf32(v.z); v.w = to_tf32(v.w);
    ((float4*)out)[i] = v;
}

// ---------------------------------------------------------------------------
// Weight transpose + tf32 round: W[K,N] -> T[N,K]
// ---------------------------------------------------------------------------
__global__ void transpose_tf32(const float* __restrict__ W, int K, int N,
                               float* __restrict__ T)
{
    __shared__ float ts[32][33];
    const int n0 = blockIdx.x * 32, k0 = blockIdx.y * 32;
    const int tx = threadIdx.x, ty = threadIdx.y;
#pragma unroll
    for (int i = 0; i < 4; i++)
        ts[ty + i * 8][tx] = W[(size_t)(k0 + ty + i * 8) * N + n0 + tx];
    __syncthreads();
#pragma unroll
    for (int i = 0; i < 4; i++)
        T[(size_t)(n0 + ty + i * 8) * K + k0 + tx] = to_tf32(ts[tx][ty + i * 8]);
}

// ---------------------------------------------------------------------------
// Causal depthwise conv (K=4) + bias + silu; outputs exact act + rounded copy
// ---------------------------------------------------------------------------
__global__ __launch_bounds__(256)
void conv_silu(const float* __restrict__ xz, const float* __restrict__ w,
               const float* __restrict__ cb, float* __restrict__ act,
               float* __restrict__ act_t)
{
    const int idx = blockIdx.x * 256 + threadIdx.x;
    if (idx >= MTOT * DINNER) return;
    const int d = idx & (DINNER - 1);
    const int bt = idx >> 11;
    const int t = bt & (LSEQ - 1);

    float s = __ldg(cb + d);
#pragma unroll
    for (int k = 0; k < KCONV; k++) {
        const int tt = t - (KCONV - 1) + k;
        if (tt >= 0)
            s = fmaf(__ldg(w + d * KCONV + k), xz[idx + (k - (KCONV - 1)) * DINNER], s);
    }
    const float v = s / (1.f + __expf(-s));
    act[idx]   = v;
    act_t[idx] = to_tf32(v);
}

// ---------------------------------------------------------------------------
// Skinny GEMM: Bm = act @ W_B, Cm = act @ W_C
// ---------------------------------------------------------------------------
__global__ __launch_bounds__(256)
void bc_gemm(const float* __restrict__ act,
             const float* __restrict__ WB, const float* __restrict__ WC,
             float* __restrict__ Bm, float* __restrict__ Cm)
{
    const int m = blockIdx.x * 16 + (threadIdx.x >> 4);
    const int n = threadIdx.x & 15;
    const float* a = act + (size_t)m * DINNER;

    float sb = 0.f, sc = 0.f;
#pragma unroll 8
    for (int k = 0; k < DINNER; k++) {
        const float av = a[k];
        sb = fmaf(av, __ldg(WB + k * NSTATE + n), sb);
        sc = fmaf(av, __ldg(WC + k * NSTATE + n), sc);
    }
    Bm[m * NSTATE + n] = sb;
    Cm[m * NSTATE + n] = sc;
}

// ---------------------------------------------------------------------------
// Selective scan + skip + gating, MLP=8, writes tf32-rounded gated output
// ---------------------------------------------------------------------------
__global__ __launch_bounds__(256)
void scan_kernel(const float* __restrict__ delta, const float* __restrict__ act,
                 const float* __restrict__ Bm, const float* __restrict__ Cm,
                 const float* __restrict__ A_log, const float* __restrict__ D_skip,
                 const float* __restrict__ xg, float* __restrict__ gt)
{
    const int w = blockIdx.x * 8 + (threadIdx.x >> 5);   // 0 .. 2047
    const int lane = threadIdx.x & 31;
    const int n = lane & 15;
    const int b = w >> 10;
    const int dp = w & 1023;
    const int d = dp * 2 + (lane >> 4);

    const float a = -expf(A_log[d * NSTATE + n]);
    const float dsk = D_skip[d];

    const float* pD = delta + (size_t)b * LSEQ * DINNER + d;
    const float* pX = act   + (size_t)b * LSEQ * DINNER + d;
    const float* pG = xg    + (size_t)b * LSEQ * DINNER + d;
    float*       pT = gt    + (size_t)b * LSEQ * DINNER + d;
    const float* pB = Bm + (size_t)b * LSEQ * NSTATE + n;
    const float* pC = Cm + (size_t)b * LSEQ * NSTATE + n;

    float h = 0.f;
    for (int t0 = 0; t0 < LSEQ; t0 += 8) {
        float dv[8], xv[8], gv[8], bv[8], cv[8];
#pragma unroll
        for (int jj = 0; jj < 8; jj++) {
            const size_t o = (size_t)(t0 + jj) * DINNER;
            dv[jj] = pD[o];
            xv[jj] = pX[o];
            gv[jj] = pG[o];
            bv[jj] = pB[(t0 + jj) * NSTATE];
            cv[jj] = pC[(t0 + jj) * NSTATE];
        }
#pragma unroll
        for (int jj = 0; jj < 8; jj++) {
            const float dA = __expf(dv[jj] * a);
            h = fmaf(dA, h, (dv[jj] * xv[jj]) * bv[jj]);
            float p = h * cv[jj];
            p += __shfl_xor_sync(0xffffffffu, p, 1);
            p += __shfl_xor_sync(0xffffffffu, p, 2);
            p += __shfl_xor_sync(0xffffffffu, p, 4);
            p += __shfl_xor_sync(0xffffffffu, p, 8);
            if (n == 0) {
                const float g = gv[jj];
                const float y = (p + xv[jj] * dsk) * (g / (1.f + __expf(-g)));
                pT[(size_t)(t0 + jj) * DINNER] = to_tf32(y);
            }
        }
    }
}

// ---------------------------------------------------------------------------
// Launch
// ---------------------------------------------------------------------------
extern "C" void kernel_launch(void* const* d_in, const int* in_sizes, int n_in,
                              void* d_out, int out_size)
{
    const float* x      = (const float*)d_in[0];
    const float* W_in   = (const float*)d_in[1];
    const float* b_in   = (const float*)d_in[2];
    const float* W_gate = (const float*)d_in[3];
    const float* b_gate = (const float*)d_in[4];
    const float* conv_w = (const float*)d_in[5];
    const float* conv_b = (const float*)d_in[6];
    const float* A_log  = (const float*)d_in[7];
    const float* D_skip = (const float*)d_in[8];
    const float* W_delta= (const float*)d_in[9];
    const float* b_delta= (const float*)d_in[10];
    const float* W_B    = (const float*)d_in[11];
    const float* W_C    = (const float*)d_in[12];
    const float* W_out  = (const float*)d_in[13];
    const float* b_out  = (const float*)d_in[14];
    float* out = (float*)d_out;

    float *xz, *xg, *act, *delt, *Bm, *Cm, *xt, *at, *gt, *wt;
    cudaGetSymbolAddress((void**)&xz,   g_xz);
    cudaGetSymbolAddress((void**)&xg,   g_xg);
    cudaGetSymbolAddress((void**)&act,  g_act);
    cudaGetSymbolAddress((void**)&delt, g_delta);
    cudaGetSymbolAddress((void**)&Bm,   g_Bm);
    cudaGetSymbolAddress((void**)&Cm,   g_Cm);
    cudaGetSymbolAddress((void**)&xt,   g_xt);
    cudaGetSymbolAddress((void**)&at,   g_at);
    cudaGetSymbolAddress((void**)&gt,   g_gt);
    cudaGetSymbolAddress((void**)&wt,   g_wt);

    // 0) round x -> tf32
    {
        const int n4 = MTOT * DMODEL / 4;
        round_tf32<<<(n4 + 255) / 256, 256>>>(x, xt, n4);
    }
    // 1) fused in+gate: [xz | xg] = x @ [W_in | W_gate] + [b_in | b_gate]
    {
        dim3 tg(DINNER / 32, DMODEL / 32);
        transpose_tf32<<<tg, dim3(32, 8)>>>(W_in,   DMODEL, DINNER, wt);
        transpose_tf32<<<tg, dim3(32, 8)>>>(W_gate, DMODEL, DINNER,
                                            wt + (size_t)DINNER * DMODEL);
        dim3 grid(2 * DINNER / 128, MTOT / 128);     // 32 x 32
        mmagemm<0><<<grid, 256>>>(xt, wt, b_in, b_gate,
                                  xz, xg, DINNER, DINNER, DMODEL);
    }
    // 2) act = silu(conv(xz) + conv_b)  (+ tf32 copy)
    {
        const int total = MTOT * DINNER;
        conv_silu<<<(total + 255) / 256, 256>>>(xz, conv_w, conv_b, act, at);
    }
    // 3) delta = softplus(act @ W_delta + b_delta)
    {
        dim3 tg(DINNER / 32, DINNER / 32);
        transpose_tf32<<<tg, dim3(32, 8)>>>(W_delta, DINNER, DINNER, wt);
        dim3 grid(DINNER / 128, MTOT / 128);
        mmagemm<1><<<grid, 256>>>(at, wt, b_delta, b_delta,
                                  delt, delt, DINNER, DINNER, DINNER);
    }
    // 4) Bm, Cm
    {
        bc_gemm<<<MTOT / 16, 256>>>(act, W_B, W_C, Bm, Cm);
    }
    // 5) scan + skip + gating -> gt (tf32-rounded)
    {
        scan_kernel<<<(BATCH * DINNER / 2) / 8, 256>>>(delt, act, Bm, Cm,
                                                       A_log, D_skip, xg, gt);
    }
    // 6) out = gated @ W_out + b_out
    {
        dim3 tg(DMODEL / 32, DINNER / 32);
        transpose_tf32<<<tg, dim3(32, 8)>>>(W_out, DINNER, DMODEL, wt);
        dim3 grid(DMODEL / 128, MTOT / 128);
        mmagemm<0><<<grid, 256>>>(gt, wt, b_out, b_out,
                                  out, out, DMODEL, DMODEL, DINNER);
    }
}